// round 1
// baseline (speedup 1.0000x reference)
#include <cuda_runtime.h>
#include <cuda_bf16.h>
#include <cstdint>

#define N_NODES 100000
#define N_EDGES 1600000
#define FEAT 64

// ---------------- scratch (static device globals: allocation-free) ----------
__device__ float g_H[N_NODES * FEAT];   // transformed features (X @ W)
__device__ float g_A[N_NODES * FEAT];   // activation buffer (layer outputs)
__device__ float g_dinv[N_NODES];
__device__ int   g_deg[N_NODES];
__device__ int   g_rowstart[N_NODES + 1];
__device__ int   g_cursor[N_NODES];
__device__ int   g_csr_src[N_EDGES];
__device__ float g_csr_norm[N_EDGES];

// ---------------- graph preprocessing ---------------------------------------

__global__ void zero_deg_kernel() {
    int i = blockIdx.x * blockDim.x + threadIdx.x;
    if (i < N_NODES) g_deg[i] = 0;
}

__global__ void hist_kernel(const int* __restrict__ dst) {
    int e = blockIdx.x * blockDim.x + threadIdx.x;
    if (e < N_EDGES) atomicAdd(&g_deg[dst[e]], 1);
}

__global__ void dinv_kernel() {
    int i = blockIdx.x * blockDim.x + threadIdx.x;
    if (i < N_NODES) g_dinv[i] = rsqrtf((float)g_deg[i] + 1.0f);
}

// One-block chunked exclusive scan of g_deg -> g_rowstart (+ copy to g_cursor).
__global__ void scan_kernel() {
    __shared__ int warp_sums[32];
    __shared__ int carry_s;
    int tid = threadIdx.x;
    int lane = tid & 31, wid = tid >> 5;
    if (tid == 0) carry_s = 0;
    __syncthreads();
    for (int base = 0; base < N_NODES; base += 1024) {
        int i = base + tid;
        int v = (i < N_NODES) ? g_deg[i] : 0;
        // inclusive warp scan
        int x = v;
        #pragma unroll
        for (int d = 1; d < 32; d <<= 1) {
            int t = __shfl_up_sync(0xFFFFFFFFu, x, d);
            if (lane >= d) x += t;
        }
        if (lane == 31) warp_sums[wid] = x;
        __syncthreads();
        if (wid == 0) {
            int s = warp_sums[lane];
            #pragma unroll
            for (int d = 1; d < 32; d <<= 1) {
                int t = __shfl_up_sync(0xFFFFFFFFu, s, d);
                if (lane >= d) s += t;
            }
            warp_sums[lane] = s;  // inclusive
        }
        __syncthreads();
        int off = carry_s + (wid ? warp_sums[wid - 1] : 0);
        int incl = x + off;
        int excl = incl - v;
        if (i < N_NODES) {
            g_rowstart[i] = excl;
            g_cursor[i]   = excl;
        }
        __syncthreads();  // all threads have read carry_s
        if (tid == 1023) carry_s = incl;  // running total through this chunk
        __syncthreads();
    }
    if (tid == 0) g_rowstart[N_NODES] = carry_s;  // == N_EDGES
}

__global__ void csr_build_kernel(const int* __restrict__ src,
                                 const int* __restrict__ dst) {
    int e = blockIdx.x * blockDim.x + threadIdx.x;
    if (e < N_EDGES) {
        int s = src[e];
        int d = dst[e];
        int pos = atomicAdd(&g_cursor[d], 1);
        g_csr_src[pos]  = s;
        g_csr_norm[pos] = g_dinv[s] * g_dinv[d];
    }
}

// ---------------- per-layer kernels ------------------------------------------

// H = X @ W  (M=100000, K=64, N=64). Warp per row; W staged in shared.
__global__ void gemm_kernel(const float* __restrict__ X,
                            const float* __restrict__ W,
                            float* __restrict__ H) {
    __shared__ float Ws[FEAT * FEAT];  // 16 KB, row-major [k][j]
    int tid = threadIdx.x;
    for (int i = tid; i < FEAT * FEAT; i += blockDim.x) Ws[i] = W[i];
    __syncthreads();

    int lane = tid & 31, wid = tid >> 5;
    int row = blockIdx.x * 8 + wid;
    if (row >= N_NODES) return;

    const float* xr = X + (size_t)row * FEAT;
    float x0 = xr[lane];
    float x1 = xr[lane + 32];
    float a0 = 0.f, a1 = 0.f;
    #pragma unroll
    for (int k = 0; k < 32; k++) {
        float xk = __shfl_sync(0xFFFFFFFFu, x0, k);
        a0 = fmaf(xk, Ws[k * FEAT + lane],       a0);
        a1 = fmaf(xk, Ws[k * FEAT + lane + 32],  a1);
    }
    #pragma unroll
    for (int k = 0; k < 32; k++) {
        float xk = __shfl_sync(0xFFFFFFFFu, x1, k);
        a0 = fmaf(xk, Ws[(k + 32) * FEAT + lane],      a0);
        a1 = fmaf(xk, Ws[(k + 32) * FEAT + lane + 32], a1);
    }
    float* hr = g_H + (size_t)row * FEAT;
    hr[lane]      = a0;
    hr[lane + 32] = a1;
    (void)H;
}

// Gather aggregation: warp per dst node. out = sum_in norm*H[src] + dinv^2*H[row] + b  (opt relu)
__global__ void agg_kernel(const float* __restrict__ b,
                           float* __restrict__ out,
                           int relu) {
    int lane = threadIdx.x & 31, wid = threadIdx.x >> 5;
    int row = blockIdx.x * 8 + wid;
    if (row >= N_NODES) return;

    int s = g_rowstart[row];
    int e = g_rowstart[row + 1];
    float a0 = 0.f, a1 = 0.f;
    int i = s;
    // unroll-by-2 to expose memory-level parallelism on the index->data chain
    for (; i + 1 < e; i += 2) {
        int u0 = g_csr_src[i];
        int u1 = g_csr_src[i + 1];
        float n0 = g_csr_norm[i];
        float n1 = g_csr_norm[i + 1];
        const float* h0 = g_H + (size_t)u0 * FEAT;
        const float* h1 = g_H + (size_t)u1 * FEAT;
        float v00 = h0[lane], v01 = h0[lane + 32];
        float v10 = h1[lane], v11 = h1[lane + 32];
        a0 = fmaf(n0, v00, a0);
        a1 = fmaf(n0, v01, a1);
        a0 = fmaf(n1, v10, a0);
        a1 = fmaf(n1, v11, a1);
    }
    if (i < e) {
        int u = g_csr_src[i];
        float nrm = g_csr_norm[i];
        const float* hr = g_H + (size_t)u * FEAT;
        a0 = fmaf(nrm, hr[lane],      a0);
        a1 = fmaf(nrm, hr[lane + 32], a1);
    }
    // self-loop + bias
    float di = g_dinv[row];
    float sw = di * di;
    const float* hr = g_H + (size_t)row * FEAT;
    a0 = fmaf(sw, hr[lane],      a0) + b[lane];
    a1 = fmaf(sw, hr[lane + 32], a1) + b[lane + 32];
    if (relu) { a0 = fmaxf(a0, 0.f); a1 = fmaxf(a1, 0.f); }
    out[(size_t)row * FEAT + lane]      = a0;
    out[(size_t)row * FEAT + lane + 32] = a1;
}

// ---------------- launch ------------------------------------------------------

extern "C" void kernel_launch(void* const* d_in, const int* in_sizes, int n_in,
                              void* d_out, int out_size) {
    const float* x   = (const float*)d_in[0];
    const int*   ei  = (const int*)d_in[1];
    const float* W1  = (const float*)d_in[2];
    const float* b1  = (const float*)d_in[3];
    const float* W2  = (const float*)d_in[4];
    const float* b2  = (const float*)d_in[5];
    const float* W3  = (const float*)d_in[6];
    const float* b3  = (const float*)d_in[7];
    float* out = (float*)d_out;

    const int* src = ei;             // edge_index[0]
    const int* dst = ei + N_EDGES;   // edge_index[1]

    const int TB = 256;
    const int nodeBlocks = (N_NODES + TB - 1) / TB;
    const int edgeBlocks = (N_EDGES + TB - 1) / TB;
    const int warpBlocks = (N_NODES + 7) / 8;  // 8 warps (rows) per 256-thread block

    // --- preprocessing (per launch; deterministic) ---
    zero_deg_kernel<<<nodeBlocks, TB>>>();
    hist_kernel<<<edgeBlocks, TB>>>(dst);
    dinv_kernel<<<nodeBlocks, TB>>>();
    scan_kernel<<<1, 1024>>>();
    csr_build_kernel<<<edgeBlocks, TB>>>(src, dst);

    // --- layer 1: H = x @ W1 ; A = relu(agg + self + b1) ---
    gemm_kernel<<<warpBlocks, TB>>>(x, W1, g_H);
    agg_kernel<<<warpBlocks, TB>>>(b1, g_A, 1);

    // --- layer 2: H = A @ W2 ; A = relu(agg + self + b2) (in-place ok) ---
    gemm_kernel<<<warpBlocks, TB>>>(g_A, W2, g_H);
    agg_kernel<<<warpBlocks, TB>>>(b2, g_A, 1);

    // --- layer 3: H = A @ W3 ; out = agg + self + b3 (no relu) ---
    gemm_kernel<<<warpBlocks, TB>>>(g_A, W3, g_H);
    agg_kernel<<<warpBlocks, TB>>>(b3, out, 0);

    (void)in_sizes; (void)n_in; (void)out_size;
}

// round 2
// speedup vs baseline: 1.1026x; 1.1026x over previous
#include <cuda_runtime.h>
#include <cuda_bf16.h>
#include <cstdint>

#define N_NODES 100000
#define N_EDGES 1600000
#define FEAT 64

#define SCAN_TPB 1024
#define SCAN_PER_THREAD 4
#define SCAN_CHUNK (SCAN_TPB * SCAN_PER_THREAD)                      // 4096
#define SCAN_NBLOCKS ((N_NODES + SCAN_CHUNK - 1) / SCAN_CHUNK)       // 25 (<=32)

// ---------------- scratch (static device globals: allocation-free) ----------
__device__ float g_H[N_NODES * FEAT];   // transformed features (X @ W)
__device__ float g_A[N_NODES * FEAT];   // activation buffer
__device__ float g_dinv[N_NODES];
__device__ int   g_deg[N_NODES];
__device__ int   g_rowstart[N_NODES + 1];
__device__ int   g_cursor[N_NODES];
__device__ int2  g_csr[N_EDGES];        // {src, norm-as-int-bits}
__device__ int   g_blocksum[SCAN_NBLOCKS];
__device__ int   g_blockoff[SCAN_NBLOCKS];

// ---------------- graph preprocessing ---------------------------------------

__global__ void zero_deg_kernel() {
    int i = blockIdx.x * blockDim.x + threadIdx.x;   // i indexes int4
    if (i < N_NODES / 4) ((int4*)g_deg)[i] = make_int4(0, 0, 0, 0);
}

__global__ void hist_kernel(const int* __restrict__ dst) {
    int e4 = blockIdx.x * blockDim.x + threadIdx.x;
    if (e4 < N_EDGES / 4) {
        int4 d = ((const int4*)dst)[e4];
        atomicAdd(&g_deg[d.x], 1);
        atomicAdd(&g_deg[d.y], 1);
        atomicAdd(&g_deg[d.z], 1);
        atomicAdd(&g_deg[d.w], 1);
    }
}

// Pass 1: per-block exclusive scan of deg (local), block sums, and dinv.
__global__ void scan1_kernel() {
    __shared__ int warp_sums[32];
    int tid = threadIdx.x;
    int lane = tid & 31, wid = tid >> 5;
    int idx0 = blockIdx.x * SCAN_CHUNK + tid * SCAN_PER_THREAD;

    int v[SCAN_PER_THREAD];
    int sum = 0;
    #pragma unroll
    for (int j = 0; j < SCAN_PER_THREAD; j++) {
        int i = idx0 + j;
        v[j] = (i < N_NODES) ? g_deg[i] : 0;
        sum += v[j];
    }
    // warp inclusive scan of per-thread sums
    int x = sum;
    #pragma unroll
    for (int d = 1; d < 32; d <<= 1) {
        int t = __shfl_up_sync(0xFFFFFFFFu, x, d);
        if (lane >= d) x += t;
    }
    if (lane == 31) warp_sums[wid] = x;
    __syncthreads();
    if (wid == 0) {
        int s = warp_sums[lane];
        #pragma unroll
        for (int d = 1; d < 32; d <<= 1) {
            int t = __shfl_up_sync(0xFFFFFFFFu, s, d);
            if (lane >= d) s += t;
        }
        warp_sums[lane] = s;   // inclusive over warps
    }
    __syncthreads();
    int thread_excl = (x - sum) + (wid ? warp_sums[wid - 1] : 0);

    int run = thread_excl;
    #pragma unroll
    for (int j = 0; j < SCAN_PER_THREAD; j++) {
        int i = idx0 + j;
        if (i < N_NODES) {
            g_rowstart[i] = run;                       // local (block) exclusive
            g_dinv[i] = rsqrtf((float)v[j] + 1.0f);
        }
        run += v[j];
    }
    if (tid == SCAN_TPB - 1) g_blocksum[blockIdx.x] = thread_excl + sum;
}

// Pass 2: 1-warp scan of block sums (SCAN_NBLOCKS <= 32).
__global__ void scan2_kernel() {
    int lane = threadIdx.x;
    int v = (lane < SCAN_NBLOCKS) ? g_blocksum[lane] : 0;
    int x = v;
    #pragma unroll
    for (int d = 1; d < 32; d <<= 1) {
        int t = __shfl_up_sync(0xFFFFFFFFu, x, d);
        if (lane >= d) x += t;
    }
    if (lane < SCAN_NBLOCKS) g_blockoff[lane] = x - v;   // exclusive
    if (lane == 31) g_rowstart[N_NODES] = x;             // grand total = N_EDGES
}

// Pass 3: add block offsets; init cursor.
__global__ void scan3_kernel() {
    int i = blockIdx.x * blockDim.x + threadIdx.x;
    if (i < N_NODES) {
        int r = g_rowstart[i] + g_blockoff[i / SCAN_CHUNK];
        g_rowstart[i] = r;
        g_cursor[i]   = r;
    }
}

__global__ void csr_build_kernel(const int* __restrict__ src,
                                 const int* __restrict__ dst) {
    int e4 = blockIdx.x * blockDim.x + threadIdx.x;
    if (e4 < N_EDGES / 4) {
        int4 s = ((const int4*)src)[e4];
        int4 d = ((const int4*)dst)[e4];
        {
            int pos = atomicAdd(&g_cursor[d.x], 1);
            g_csr[pos] = make_int2(s.x, __float_as_int(g_dinv[s.x] * g_dinv[d.x]));
        }
        {
            int pos = atomicAdd(&g_cursor[d.y], 1);
            g_csr[pos] = make_int2(s.y, __float_as_int(g_dinv[s.y] * g_dinv[d.y]));
        }
        {
            int pos = atomicAdd(&g_cursor[d.z], 1);
            g_csr[pos] = make_int2(s.z, __float_as_int(g_dinv[s.z] * g_dinv[d.z]));
        }
        {
            int pos = atomicAdd(&g_cursor[d.w], 1);
            g_csr[pos] = make_int2(s.w, __float_as_int(g_dinv[s.w] * g_dinv[d.w]));
        }
    }
}

// ---------------- per-layer kernels ------------------------------------------

// H = X @ W  (M=100000, K=64, N=64). Warp per row; W staged in shared.
__global__ void gemm_kernel(const float* __restrict__ X,
                            const float* __restrict__ W) {
    __shared__ float Ws[FEAT * FEAT];  // 16 KB, row-major [k][j]
    int tid = threadIdx.x;
    for (int i = tid; i < FEAT * FEAT; i += blockDim.x) Ws[i] = W[i];
    __syncthreads();

    int lane = tid & 31, wid = tid >> 5;
    int row = blockIdx.x * 8 + wid;
    if (row >= N_NODES) return;

    const float* xr = X + (size_t)row * FEAT;
    float x0 = xr[lane];
    float x1 = xr[lane + 32];
    float a0 = 0.f, a1 = 0.f;
    #pragma unroll
    for (int k = 0; k < 32; k++) {
        float xk = __shfl_sync(0xFFFFFFFFu, x0, k);
        a0 = fmaf(xk, Ws[k * FEAT + lane],       a0);
        a1 = fmaf(xk, Ws[k * FEAT + lane + 32],  a1);
    }
    #pragma unroll
    for (int k = 0; k < 32; k++) {
        float xk = __shfl_sync(0xFFFFFFFFu, x1, k);
        a0 = fmaf(xk, Ws[(k + 32) * FEAT + lane],      a0);
        a1 = fmaf(xk, Ws[(k + 32) * FEAT + lane + 32], a1);
    }
    float* hr = g_H + (size_t)row * FEAT;
    hr[lane]      = a0;
    hr[lane + 32] = a1;
}

// Gather aggregation: warp per dst row, HALF-WARP per edge, float4 lanes.
// lanes 0-15 handle even edge, lanes 16-31 odd edge; lane covers 4 feats.
__global__ void agg_kernel(const float* __restrict__ b,
                           float* __restrict__ out,
                           int relu) {
    int lane = threadIdx.x & 31, wid = threadIdx.x >> 5;
    int row = blockIdx.x * 8 + wid;
    if (row >= N_NODES) return;

    int s = g_rowstart[row];
    int e = g_rowstart[row + 1];
    int half = lane >> 4;        // 0 or 1
    int fl   = lane & 15;        // float4 index within 64-float row

    float4 acc = make_float4(0.f, 0.f, 0.f, 0.f);
    #pragma unroll 4
    for (int i = s; i < e; i += 2) {
        int idx = i + half;
        int u; float nrm;
        if (idx < e) {
            int2 p = g_csr[idx];
            u = p.x;
            nrm = __int_as_float(p.y);
        } else {
            u = row;              // safe dummy address
            nrm = 0.f;
        }
        float4 v = ((const float4*)(g_H + (size_t)u * FEAT))[fl];
        acc.x = fmaf(nrm, v.x, acc.x);
        acc.y = fmaf(nrm, v.y, acc.y);
        acc.z = fmaf(nrm, v.z, acc.z);
        acc.w = fmaf(nrm, v.w, acc.w);
    }
    // combine odd/even halves (lane L += lane L+16)
    acc.x += __shfl_xor_sync(0xFFFFFFFFu, acc.x, 16);
    acc.y += __shfl_xor_sync(0xFFFFFFFFu, acc.y, 16);
    acc.z += __shfl_xor_sync(0xFFFFFFFFu, acc.z, 16);
    acc.w += __shfl_xor_sync(0xFFFFFFFFu, acc.w, 16);

    if (half == 0) {
        float di = g_dinv[row];
        float sw = di * di;
        float4 v  = ((const float4*)(g_H + (size_t)row * FEAT))[fl];
        float4 bv = ((const float4*)b)[fl];
        acc.x = fmaf(sw, v.x, acc.x) + bv.x;
        acc.y = fmaf(sw, v.y, acc.y) + bv.y;
        acc.z = fmaf(sw, v.z, acc.z) + bv.z;
        acc.w = fmaf(sw, v.w, acc.w) + bv.w;
        if (relu) {
            acc.x = fmaxf(acc.x, 0.f);
            acc.y = fmaxf(acc.y, 0.f);
            acc.z = fmaxf(acc.z, 0.f);
            acc.w = fmaxf(acc.w, 0.f);
        }
        ((float4*)(out + (size_t)row * FEAT))[fl] = acc;
    }
}

// ---------------- launch ------------------------------------------------------

extern "C" void kernel_launch(void* const* d_in, const int* in_sizes, int n_in,
                              void* d_out, int out_size) {
    const float* x   = (const float*)d_in[0];
    const int*   ei  = (const int*)d_in[1];
    const float* W1  = (const float*)d_in[2];
    const float* b1  = (const float*)d_in[3];
    const float* W2  = (const float*)d_in[4];
    const float* b2  = (const float*)d_in[5];
    const float* W3  = (const float*)d_in[6];
    const float* b3  = (const float*)d_in[7];
    float* out = (float*)d_out;

    const int* src = ei;             // edge_index[0]
    const int* dst = ei + N_EDGES;   // edge_index[1]

    const int TB = 256;
    const int nodeBlocks   = (N_NODES + TB - 1) / TB;
    const int node4Blocks  = (N_NODES / 4 + TB - 1) / TB;
    const int edge4Blocks  = (N_EDGES / 4 + TB - 1) / TB;
    const int warpBlocks   = (N_NODES + 7) / 8;   // 8 rows per 256-thread block

    // --- preprocessing (per launch; deterministic up to fp-sum order) ---
    zero_deg_kernel<<<node4Blocks, TB>>>();
    hist_kernel<<<edge4Blocks, TB>>>(dst);
    scan1_kernel<<<SCAN_NBLOCKS, SCAN_TPB>>>();
    scan2_kernel<<<1, 32>>>();
    scan3_kernel<<<nodeBlocks, TB>>>();
    csr_build_kernel<<<edge4Blocks, TB>>>(src, dst);

    // --- layer 1 ---
    gemm_kernel<<<warpBlocks, TB>>>(x, W1);
    agg_kernel<<<warpBlocks, TB>>>(b1, g_A, 1);
    // --- layer 2 ---
    gemm_kernel<<<warpBlocks, TB>>>(g_A, W2);
    agg_kernel<<<warpBlocks, TB>>>(b2, g_A, 1);
    // --- layer 3 ---
    gemm_kernel<<<warpBlocks, TB>>>(g_A, W3);
    agg_kernel<<<warpBlocks, TB>>>(b3, out, 0);

    (void)in_sizes; (void)n_in; (void)out_size;
}

// round 3
// speedup vs baseline: 1.4000x; 1.2697x over previous
#include <cuda_runtime.h>
#include <cuda_bf16.h>
#include <cstdint>

#define N_NODES 100000
#define N_EDGES 1600000
#define FEAT 64

#define SCAN_TPB 1024
#define SCAN_PER_THREAD 4
#define SCAN_CHUNK (SCAN_TPB * SCAN_PER_THREAD)                      // 4096
#define SCAN_NBLOCKS ((N_NODES + SCAN_CHUNK - 1) / SCAN_CHUNK)       // 25 (<=148: co-resident)
#define FLAG_VALID (1 << 30)
#define FLAG_MASK  (FLAG_VALID - 1)

// ---------------- scratch (static device globals: allocation-free) ----------
__device__ float g_H[N_NODES * FEAT];   // transformed features (X @ W)
__device__ float g_A[N_NODES * FEAT];   // activation buffer
__device__ float g_dinv[N_NODES];
__device__ int   g_rowstart[N_NODES + 1];
__device__ int   g_cursor[N_NODES];
__device__ int2  g_csr[N_EDGES];        // {src, norm-as-int-bits}
// deg[N_NODES] followed by lookback flags[64]; zeroed by ONE memset per launch
__device__ int   g_zr[N_NODES + 64];

// ---------------- graph preprocessing ---------------------------------------

__global__ void hist_kernel(const int* __restrict__ dst) {
    int e4 = blockIdx.x * blockDim.x + threadIdx.x;
    if (e4 < N_EDGES / 4) {
        int4 d = ((const int4*)dst)[e4];
        atomicAdd(&g_zr[d.x], 1);
        atomicAdd(&g_zr[d.y], 1);
        atomicAdd(&g_zr[d.z], 1);
        atomicAdd(&g_zr[d.w], 1);
    }
}

// Single-pass chained-lookback scan: deg -> rowstart/cursor, plus dinv.
__global__ void scan_kernel() {
    __shared__ int warp_sums[32];
    __shared__ int prefix_s;
    int tid = threadIdx.x;
    int lane = tid & 31, wid = tid >> 5;
    int b = blockIdx.x;
    int idx0 = b * SCAN_CHUNK + tid * SCAN_PER_THREAD;

    int v[SCAN_PER_THREAD];
    int sum = 0;
    #pragma unroll
    for (int j = 0; j < SCAN_PER_THREAD; j++) {
        int i = idx0 + j;
        v[j] = (i < N_NODES) ? g_zr[i] : 0;
        sum += v[j];
    }
    // warp inclusive scan of per-thread sums
    int x = sum;
    #pragma unroll
    for (int d = 1; d < 32; d <<= 1) {
        int t = __shfl_up_sync(0xFFFFFFFFu, x, d);
        if (lane >= d) x += t;
    }
    if (lane == 31) warp_sums[wid] = x;
    __syncthreads();
    if (wid == 0) {
        int s = warp_sums[lane];
        #pragma unroll
        for (int d = 1; d < 32; d <<= 1) {
            int t = __shfl_up_sync(0xFFFFFFFFu, s, d);
            if (lane >= d) s += t;
        }
        warp_sums[lane] = s;   // inclusive over warps
    }
    __syncthreads();
    int thread_excl = (x - sum) + (wid ? warp_sums[wid - 1] : 0);
    int block_total = warp_sums[31];

    // chained lookback: thread 0 gets predecessor's inclusive prefix, publishes ours
    if (tid == 0) {
        int pre = 0;
        if (b > 0) {
            int f;
            do { f = atomicAdd(&g_zr[N_NODES + b - 1], 0); } while (f == 0);
            pre = f & FLAG_MASK;
        }
        __threadfence();
        atomicExch(&g_zr[N_NODES + b], FLAG_VALID | (pre + block_total));
        prefix_s = pre;
        if (b == SCAN_NBLOCKS - 1) g_rowstart[N_NODES] = pre + block_total;
    }
    __syncthreads();
    int base = prefix_s + thread_excl;

    int run = base;
    #pragma unroll
    for (int j = 0; j < SCAN_PER_THREAD; j++) {
        int i = idx0 + j;
        if (i < N_NODES) {
            g_rowstart[i] = run;
            g_cursor[i]   = run;
            g_dinv[i] = rsqrtf((float)v[j] + 1.0f);
        }
        run += v[j];
    }
}

__global__ void csr_build_kernel(const int* __restrict__ src,
                                 const int* __restrict__ dst) {
    int e4 = blockIdx.x * blockDim.x + threadIdx.x;
    if (e4 < N_EDGES / 4) {
        int4 s = ((const int4*)src)[e4];
        int4 d = ((const int4*)dst)[e4];
        {
            int pos = atomicAdd(&g_cursor[d.x], 1);
            g_csr[pos] = make_int2(s.x, __float_as_int(g_dinv[s.x] * g_dinv[d.x]));
        }
        {
            int pos = atomicAdd(&g_cursor[d.y], 1);
            g_csr[pos] = make_int2(s.y, __float_as_int(g_dinv[s.y] * g_dinv[d.y]));
        }
        {
            int pos = atomicAdd(&g_cursor[d.z], 1);
            g_csr[pos] = make_int2(s.z, __float_as_int(g_dinv[s.z] * g_dinv[d.z]));
        }
        {
            int pos = atomicAdd(&g_cursor[d.w], 1);
            g_csr[pos] = make_int2(s.w, __float_as_int(g_dinv[s.w] * g_dinv[d.w]));
        }
    }
}

// ---------------- per-layer kernels ------------------------------------------

// Tiled GEMM: H = X @ W. Block = 64 rows x 64 cols, 256 threads, 4x4 per thread.
__global__ __launch_bounds__(256) void gemm_kernel(const float* __restrict__ X,
                                                   const float* __restrict__ W) {
    __shared__ float Xs[64][64];   // row-major [r][k]
    __shared__ float Ws[64][64];   // row-major [k][c]
    int tid = threadIdx.x;
    int row0 = blockIdx.x * 64;

    // load W tile (4096 floats, coalesced float4)
    {
        const float4* W4 = (const float4*)W;
        float4* Ws4 = (float4*)Ws;
        #pragma unroll
        for (int i = 0; i < 4; i++) Ws4[tid + 256 * i] = W4[tid + 256 * i];
    }
    // load X tile (coalesced float4; rows beyond N zeroed)
    {
        float4* Xs4 = (float4*)Xs;
        const float4* X4 = (const float4*)X;
        #pragma unroll
        for (int i = 0; i < 4; i++) {
            int li = tid + 256 * i;            // float4 index in tile
            int grow = row0 + (li >> 4);
            Xs4[li] = (grow < N_NODES) ? X4[(size_t)grow * 16 + (li & 15)]
                                       : make_float4(0.f, 0.f, 0.f, 0.f);
        }
    }
    __syncthreads();

    int tc = tid & 15;   // col group: cols 4*tc .. 4*tc+3
    int tr = tid >> 4;   // row group: rows 4*tr .. 4*tr+3

    float acc[4][4];
    #pragma unroll
    for (int i = 0; i < 4; i++)
        #pragma unroll
        for (int j = 0; j < 4; j++) acc[i][j] = 0.f;

    #pragma unroll 8
    for (int k = 0; k < 64; k++) {
        float4 bq = *(const float4*)&Ws[k][4 * tc];
        float a0 = Xs[4 * tr + 0][k];
        float a1 = Xs[4 * tr + 1][k];
        float a2 = Xs[4 * tr + 2][k];
        float a3 = Xs[4 * tr + 3][k];
        acc[0][0] = fmaf(a0, bq.x, acc[0][0]);
        acc[0][1] = fmaf(a0, bq.y, acc[0][1]);
        acc[0][2] = fmaf(a0, bq.z, acc[0][2]);
        acc[0][3] = fmaf(a0, bq.w, acc[0][3]);
        acc[1][0] = fmaf(a1, bq.x, acc[1][0]);
        acc[1][1] = fmaf(a1, bq.y, acc[1][1]);
        acc[1][2] = fmaf(a1, bq.z, acc[1][2]);
        acc[1][3] = fmaf(a1, bq.w, acc[1][3]);
        acc[2][0] = fmaf(a2, bq.x, acc[2][0]);
        acc[2][1] = fmaf(a2, bq.y, acc[2][1]);
        acc[2][2] = fmaf(a2, bq.z, acc[2][2]);
        acc[2][3] = fmaf(a2, bq.w, acc[2][3]);
        acc[3][0] = fmaf(a3, bq.x, acc[3][0]);
        acc[3][1] = fmaf(a3, bq.y, acc[3][1]);
        acc[3][2] = fmaf(a3, bq.z, acc[3][2]);
        acc[3][3] = fmaf(a3, bq.w, acc[3][3]);
    }

    #pragma unroll
    for (int i = 0; i < 4; i++) {
        int grow = row0 + 4 * tr + i;
        if (grow < N_NODES) {
            float4 o = make_float4(acc[i][0], acc[i][1], acc[i][2], acc[i][3]);
            ((float4*)(g_H + (size_t)grow * FEAT))[tc] = o;
        }
    }
}

// Gather aggregation: warp per dst row, HALF-WARP per edge, float4 lanes.
__global__ void agg_kernel(const float* __restrict__ b,
                           float* __restrict__ out,
                           int relu) {
    int lane = threadIdx.x & 31, wid = threadIdx.x >> 5;
    int row = blockIdx.x * 8 + wid;
    if (row >= N_NODES) return;

    int s = g_rowstart[row];
    int e = g_rowstart[row + 1];
    int half = lane >> 4;        // 0 or 1
    int fl   = lane & 15;        // float4 index within 64-float row

    float4 acc = make_float4(0.f, 0.f, 0.f, 0.f);
    #pragma unroll 4
    for (int i = s; i < e; i += 2) {
        int idx = i + half;
        int u; float nrm;
        if (idx < e) {
            int2 p = g_csr[idx];
            u = p.x;
            nrm = __int_as_float(p.y);
        } else {
            u = row;
            nrm = 0.f;
        }
        float4 v = ((const float4*)(g_H + (size_t)u * FEAT))[fl];
        acc.x = fmaf(nrm, v.x, acc.x);
        acc.y = fmaf(nrm, v.y, acc.y);
        acc.z = fmaf(nrm, v.z, acc.z);
        acc.w = fmaf(nrm, v.w, acc.w);
    }
    acc.x += __shfl_xor_sync(0xFFFFFFFFu, acc.x, 16);
    acc.y += __shfl_xor_sync(0xFFFFFFFFu, acc.y, 16);
    acc.z += __shfl_xor_sync(0xFFFFFFFFu, acc.z, 16);
    acc.w += __shfl_xor_sync(0xFFFFFFFFu, acc.w, 16);

    if (half == 0) {
        float di = g_dinv[row];
        float sw = di * di;
        float4 v  = ((const float4*)(g_H + (size_t)row * FEAT))[fl];
        float4 bv = ((const float4*)b)[fl];
        acc.x = fmaf(sw, v.x, acc.x) + bv.x;
        acc.y = fmaf(sw, v.y, acc.y) + bv.y;
        acc.z = fmaf(sw, v.z, acc.z) + bv.z;
        acc.w = fmaf(sw, v.w, acc.w) + bv.w;
        if (relu) {
            acc.x = fmaxf(acc.x, 0.f);
            acc.y = fmaxf(acc.y, 0.f);
            acc.z = fmaxf(acc.z, 0.f);
            acc.w = fmaxf(acc.w, 0.f);
        }
        ((float4*)(out + (size_t)row * FEAT))[fl] = acc;
    }
}

// ---------------- launch ------------------------------------------------------

extern "C" void kernel_launch(void* const* d_in, const int* in_sizes, int n_in,
                              void* d_out, int out_size) {
    const float* x   = (const float*)d_in[0];
    const int*   ei  = (const int*)d_in[1];
    const float* W1  = (const float*)d_in[2];
    const float* b1  = (const float*)d_in[3];
    const float* W2  = (const float*)d_in[4];
    const float* b2  = (const float*)d_in[5];
    const float* W3  = (const float*)d_in[6];
    const float* b3  = (const float*)d_in[7];
    float* out = (float*)d_out;

    const int* src = ei;             // edge_index[0]
    const int* dst = ei + N_EDGES;   // edge_index[1]

    const int TB = 256;
    const int edge4Blocks = (N_EDGES / 4 + TB - 1) / TB;
    const int warpBlocks  = (N_NODES + 7) / 8;    // agg: 8 rows/block
    const int gemmBlocks  = (N_NODES + 63) / 64;  // gemm: 64 rows/block

    // zero deg + lookback flags in one memset (graph memset node, not a kernel)
    void* zr_ptr = nullptr;
    cudaGetSymbolAddress(&zr_ptr, g_zr);
    cudaMemsetAsync(zr_ptr, 0, sizeof(int) * (N_NODES + 64));

    // kernel launches: hist(0) scan(1) csr(2) gemm1(3)<-profiled agg1(4) ...
    hist_kernel<<<edge4Blocks, TB>>>(dst);
    scan_kernel<<<SCAN_NBLOCKS, SCAN_TPB>>>();
    csr_build_kernel<<<edge4Blocks, TB>>>(src, dst);

    gemm_kernel<<<gemmBlocks, TB>>>(x, W1);
    agg_kernel<<<warpBlocks, TB>>>(b1, g_A, 1);

    gemm_kernel<<<gemmBlocks, TB>>>(g_A, W2);
    agg_kernel<<<warpBlocks, TB>>>(b2, g_A, 1);

    gemm_kernel<<<gemmBlocks, TB>>>(g_A, W3);
    agg_kernel<<<warpBlocks, TB>>>(b3, out, 0);

    (void)in_sizes; (void)n_in; (void)out_size;
}

// round 4
// speedup vs baseline: 1.4002x; 1.0001x over previous
#include <cuda_runtime.h>
#include <cuda_bf16.h>
#include <cstdint>

#define N_NODES 100000
#define N_EDGES 1600000
#define FEAT 64

#define SCAN_TPB 1024
#define SCAN_PER_THREAD 4
#define SCAN_CHUNK (SCAN_TPB * SCAN_PER_THREAD)                      // 4096
#define SCAN_NBLOCKS ((N_NODES + SCAN_CHUNK - 1) / SCAN_CHUNK)       // 25 (<=148: co-resident)
#define FLAG_VALID (1 << 30)
#define FLAG_MASK  (FLAG_VALID - 1)

// ---------------- scratch (static device globals: allocation-free) ----------
__device__ float g_H[N_NODES * FEAT];   // transformed features (X @ W)
__device__ float g_A[N_NODES * FEAT];   // activation buffer
__device__ float g_dinv[N_NODES];
__device__ int   g_rowstart[N_NODES + 1];
__device__ int   g_cursor[N_NODES];
__device__ int2  g_csr[N_EDGES];        // {src, norm-as-int-bits}
// deg[N_NODES] followed by lookback flags[64]; zeroed by ONE memset per launch
__device__ int   g_zr[N_NODES + 64];

// ---------------- GEMM body (used by fused kernel and standalone) ------------

__device__ __forceinline__ void gemm_body(const float* __restrict__ X,
                                          const float* __restrict__ W,
                                          int row0, int tid,
                                          float (*Xs)[64], float (*Ws)[64]) {
    // load W tile (4096 floats, coalesced float4)
    {
        const float4* W4 = (const float4*)W;
        float4* Ws4 = (float4*)Ws;
        #pragma unroll
        for (int i = 0; i < 4; i++) Ws4[tid + 256 * i] = W4[tid + 256 * i];
    }
    // load X tile
    {
        float4* Xs4 = (float4*)Xs;
        const float4* X4 = (const float4*)X;
        #pragma unroll
        for (int i = 0; i < 4; i++) {
            int li = tid + 256 * i;
            int grow = row0 + (li >> 4);
            Xs4[li] = (grow < N_NODES) ? X4[(size_t)grow * 16 + (li & 15)]
                                       : make_float4(0.f, 0.f, 0.f, 0.f);
        }
    }
    __syncthreads();

    int tc = tid & 15;
    int tr = tid >> 4;

    float acc[4][4];
    #pragma unroll
    for (int i = 0; i < 4; i++)
        #pragma unroll
        for (int j = 0; j < 4; j++) acc[i][j] = 0.f;

    #pragma unroll 8
    for (int k = 0; k < 64; k++) {
        float4 bq = *(const float4*)&Ws[k][4 * tc];
        float a0 = Xs[4 * tr + 0][k];
        float a1 = Xs[4 * tr + 1][k];
        float a2 = Xs[4 * tr + 2][k];
        float a3 = Xs[4 * tr + 3][k];
        acc[0][0] = fmaf(a0, bq.x, acc[0][0]);
        acc[0][1] = fmaf(a0, bq.y, acc[0][1]);
        acc[0][2] = fmaf(a0, bq.z, acc[0][2]);
        acc[0][3] = fmaf(a0, bq.w, acc[0][3]);
        acc[1][0] = fmaf(a1, bq.x, acc[1][0]);
        acc[1][1] = fmaf(a1, bq.y, acc[1][1]);
        acc[1][2] = fmaf(a1, bq.z, acc[1][2]);
        acc[1][3] = fmaf(a1, bq.w, acc[1][3]);
        acc[2][0] = fmaf(a2, bq.x, acc[2][0]);
        acc[2][1] = fmaf(a2, bq.y, acc[2][1]);
        acc[2][2] = fmaf(a2, bq.z, acc[2][2]);
        acc[2][3] = fmaf(a2, bq.w, acc[2][3]);
        acc[3][0] = fmaf(a3, bq.x, acc[3][0]);
        acc[3][1] = fmaf(a3, bq.y, acc[3][1]);
        acc[3][2] = fmaf(a3, bq.z, acc[3][2]);
        acc[3][3] = fmaf(a3, bq.w, acc[3][3]);
    }

    #pragma unroll
    for (int i = 0; i < 4; i++) {
        int grow = row0 + 4 * tr + i;
        if (grow < N_NODES) {
            float4 o = make_float4(acc[i][0], acc[i][1], acc[i][2], acc[i][3]);
            ((float4*)(g_H + (size_t)grow * FEAT))[tc] = o;
        }
    }
}

// Fused: blocks [0, gemmBlocks) do gemm1; the rest do the degree histogram.
// The two are fully independent -> overlap fma-bound and atomic-bound work.
__global__ __launch_bounds__(256) void gemm1_hist_kernel(const float* __restrict__ X,
                                                         const float* __restrict__ W,
                                                         const int* __restrict__ dst,
                                                         int gemmBlocks) {
    __shared__ float Xs[64][64];
    __shared__ float Ws[64][64];
    int bid = blockIdx.x;
    if (bid < gemmBlocks) {
        gemm_body(X, W, bid * 64, threadIdx.x, Xs, Ws);
    } else {
        int e4 = (bid - gemmBlocks) * blockDim.x + threadIdx.x;
        if (e4 < N_EDGES / 4) {
            int4 d = ((const int4*)dst)[e4];
            atomicAdd(&g_zr[d.x], 1);
            atomicAdd(&g_zr[d.y], 1);
            atomicAdd(&g_zr[d.z], 1);
            atomicAdd(&g_zr[d.w], 1);
        }
    }
}

__global__ __launch_bounds__(256) void gemm_kernel(const float* __restrict__ X,
                                                   const float* __restrict__ W) {
    __shared__ float Xs[64][64];
    __shared__ float Ws[64][64];
    gemm_body(X, W, blockIdx.x * 64, threadIdx.x, Xs, Ws);
}

// ---------------- graph preprocessing ---------------------------------------

// Single-pass chained-lookback scan: deg -> rowstart/cursor, plus dinv.
__global__ void scan_kernel() {
    __shared__ int warp_sums[32];
    __shared__ int prefix_s;
    int tid = threadIdx.x;
    int lane = tid & 31, wid = tid >> 5;
    int b = blockIdx.x;
    int idx0 = b * SCAN_CHUNK + tid * SCAN_PER_THREAD;

    int v[SCAN_PER_THREAD];
    int sum = 0;
    #pragma unroll
    for (int j = 0; j < SCAN_PER_THREAD; j++) {
        int i = idx0 + j;
        v[j] = (i < N_NODES) ? g_zr[i] : 0;
        sum += v[j];
    }
    int x = sum;
    #pragma unroll
    for (int d = 1; d < 32; d <<= 1) {
        int t = __shfl_up_sync(0xFFFFFFFFu, x, d);
        if (lane >= d) x += t;
    }
    if (lane == 31) warp_sums[wid] = x;
    __syncthreads();
    if (wid == 0) {
        int s = warp_sums[lane];
        #pragma unroll
        for (int d = 1; d < 32; d <<= 1) {
            int t = __shfl_up_sync(0xFFFFFFFFu, s, d);
            if (lane >= d) s += t;
        }
        warp_sums[lane] = s;
    }
    __syncthreads();
    int thread_excl = (x - sum) + (wid ? warp_sums[wid - 1] : 0);
    int block_total = warp_sums[31];

    if (tid == 0) {
        int pre = 0;
        if (b > 0) {
            int f;
            do { f = atomicAdd(&g_zr[N_NODES + b - 1], 0); } while (f == 0);
            pre = f & FLAG_MASK;
        }
        __threadfence();
        atomicExch(&g_zr[N_NODES + b], FLAG_VALID | (pre + block_total));
        prefix_s = pre;
        if (b == SCAN_NBLOCKS - 1) g_rowstart[N_NODES] = pre + block_total;
    }
    __syncthreads();
    int run = prefix_s + thread_excl;

    #pragma unroll
    for (int j = 0; j < SCAN_PER_THREAD; j++) {
        int i = idx0 + j;
        if (i < N_NODES) {
            g_rowstart[i] = run;
            g_cursor[i]   = run;
            g_dinv[i] = rsqrtf((float)v[j] + 1.0f);
        }
        run += v[j];
    }
}

__global__ void csr_build_kernel(const int* __restrict__ src,
                                 const int* __restrict__ dst) {
    int e4 = blockIdx.x * blockDim.x + threadIdx.x;
    if (e4 < N_EDGES / 4) {
        int4 s = ((const int4*)src)[e4];
        int4 d = ((const int4*)dst)[e4];
        {
            int pos = atomicAdd(&g_cursor[d.x], 1);
            g_csr[pos] = make_int2(s.x, __float_as_int(g_dinv[s.x] * g_dinv[d.x]));
        }
        {
            int pos = atomicAdd(&g_cursor[d.y], 1);
            g_csr[pos] = make_int2(s.y, __float_as_int(g_dinv[s.y] * g_dinv[d.y]));
        }
        {
            int pos = atomicAdd(&g_cursor[d.z], 1);
            g_csr[pos] = make_int2(s.z, __float_as_int(g_dinv[s.z] * g_dinv[d.z]));
        }
        {
            int pos = atomicAdd(&g_cursor[d.w], 1);
            g_csr[pos] = make_int2(s.w, __float_as_int(g_dinv[s.w] * g_dinv[d.w]));
        }
    }
}

// ---------------- aggregation -------------------------------------------------
// Warp per dst row; half-warp per edge; 16 edges per warp-iteration (8 per half)
// so 8 independent 128-bit H loads are in flight per half-warp.
__global__ __launch_bounds__(256) void agg_kernel(const float* __restrict__ b,
                                                  float* __restrict__ out,
                                                  int relu) {
    int lane = threadIdx.x & 31, wid = threadIdx.x >> 5;
    int row = blockIdx.x * 8 + wid;
    if (row >= N_NODES) return;

    int s = g_rowstart[row];
    int e = g_rowstart[row + 1];
    int half = lane >> 4;        // 0 or 1
    int fl   = lane & 15;        // float4 index within 64-float row

    float4 acc = make_float4(0.f, 0.f, 0.f, 0.f);
    for (int base = s; base < e; base += 16) {
        int i0 = base + half * 8;
        int u[8]; float nm[8];
        #pragma unroll
        for (int j = 0; j < 8; j++) {
            int idx = i0 + j;
            int2 p = g_csr[idx < e ? idx : s];   // clamp: dupes get nrm=0
            u[j]  = p.x;
            nm[j] = (idx < e) ? __int_as_float(p.y) : 0.f;
        }
        float4 v[8];
        #pragma unroll
        for (int j = 0; j < 8; j++)
            v[j] = ((const float4*)(g_H + (size_t)u[j] * FEAT))[fl];
        #pragma unroll
        for (int j = 0; j < 8; j++) {
            acc.x = fmaf(nm[j], v[j].x, acc.x);
            acc.y = fmaf(nm[j], v[j].y, acc.y);
            acc.z = fmaf(nm[j], v[j].z, acc.z);
            acc.w = fmaf(nm[j], v[j].w, acc.w);
        }
    }
    acc.x += __shfl_xor_sync(0xFFFFFFFFu, acc.x, 16);
    acc.y += __shfl_xor_sync(0xFFFFFFFFu, acc.y, 16);
    acc.z += __shfl_xor_sync(0xFFFFFFFFu, acc.z, 16);
    acc.w += __shfl_xor_sync(0xFFFFFFFFu, acc.w, 16);

    if (half == 0) {
        float di = g_dinv[row];
        float sw = di * di;
        float4 v  = ((const float4*)(g_H + (size_t)row * FEAT))[fl];
        float4 bv = ((const float4*)b)[fl];
        acc.x = fmaf(sw, v.x, acc.x) + bv.x;
        acc.y = fmaf(sw, v.y, acc.y) + bv.y;
        acc.z = fmaf(sw, v.z, acc.z) + bv.z;
        acc.w = fmaf(sw, v.w, acc.w) + bv.w;
        if (relu) {
            acc.x = fmaxf(acc.x, 0.f);
            acc.y = fmaxf(acc.y, 0.f);
            acc.z = fmaxf(acc.z, 0.f);
            acc.w = fmaxf(acc.w, 0.f);
        }
        ((float4*)(out + (size_t)row * FEAT))[fl] = acc;
    }
}

// ---------------- launch ------------------------------------------------------

extern "C" void kernel_launch(void* const* d_in, const int* in_sizes, int n_in,
                              void* d_out, int out_size) {
    const float* x   = (const float*)d_in[0];
    const int*   ei  = (const int*)d_in[1];
    const float* W1  = (const float*)d_in[2];
    const float* b1  = (const float*)d_in[3];
    const float* W2  = (const float*)d_in[4];
    const float* b2  = (const float*)d_in[5];
    const float* W3  = (const float*)d_in[6];
    const float* b3  = (const float*)d_in[7];
    float* out = (float*)d_out;

    const int* src = ei;             // edge_index[0]
    const int* dst = ei + N_EDGES;   // edge_index[1]

    const int TB = 256;
    const int edge4Blocks = (N_EDGES / 4 + TB - 1) / TB;   // 1563
    const int warpBlocks  = (N_NODES + 7) / 8;             // agg: 8 rows/block
    const int gemmBlocks  = (N_NODES + 63) / 64;           // 1563

    // zero deg + lookback flags in one memset (graph memset node, not a kernel)
    void* zr_ptr = nullptr;
    cudaGetSymbolAddress(&zr_ptr, g_zr);
    cudaMemsetAsync(zr_ptr, 0, sizeof(int) * (N_NODES + 64));

    // kernels: fused(0) scan(1) csr(2) agg1(3)<-profiled gemm2(4) agg2(5) ...
    gemm1_hist_kernel<<<gemmBlocks + edge4Blocks, TB>>>(x, W1, dst, gemmBlocks);
    scan_kernel<<<SCAN_NBLOCKS, SCAN_TPB>>>();
    csr_build_kernel<<<edge4Blocks, TB>>>(src, dst);

    agg_kernel<<<warpBlocks, TB>>>(b1, g_A, 1);

    gemm_kernel<<<gemmBlocks, TB>>>(g_A, W2);
    agg_kernel<<<warpBlocks, TB>>>(b2, g_A, 1);

    gemm_kernel<<<gemmBlocks, TB>>>(g_A, W3);
    agg_kernel<<<warpBlocks, TB>>>(b3, out, 0);

    (void)in_sizes; (void)n_in; (void)out_size;
}